// round 12
// baseline (speedup 1.0000x reference)
#include <cuda_runtime.h>
#include <cstdint>
#include <math.h>

#define D_DIM    256
#define M_TOT    8192
#define N_TOT    8192
#define TM       64
#define TN       256
#define NTHREADS 256
#define KCH      32
#define TOTCH    ((N_TOT / TN) * (D_DIM / KCH))   // 256
#define CAND_MAX 256
#define NBUF     4

#define SM_A_FLOATS (TM * D_DIM)          // 16384 floats = 64 KB
#define BUF_FLOATS  (TN * 40)             // 10240 floats = 40 KB (row stride 40)
#define SM_BYTES    (SM_A_FLOATS * 4 + NBUF * BUF_FLOATS * 4)   // 229376 = 224 KB

__device__ float    g_bpk[N_TOT * D_DIM];
__device__ float    g_esq[N_TOT];
__device__ int      g_cand[M_TOT * CAND_MAX];
__device__ int      g_cnt[M_TOT];
__device__ unsigned g_mx2, g_me2;   // atomicMax-idempotent across graph replays

// ---------------------------------------------------------------------------
__device__ __forceinline__ float tf32_rn(float a) {
    uint32_t u;
    asm("cvt.rna.tf32.f32 %0, %1;" : "=r"(u) : "f"(a));
    return __uint_as_float(u);
}
__device__ __forceinline__ void mma_f(float* d, float4 a, float2 b) {
    asm volatile(
        "mma.sync.aligned.m16n8k8.row.col.f32.tf32.tf32.f32 "
        "{%0,%1,%2,%3}, {%4,%5,%6,%7}, {%8,%9}, {%0,%1,%2,%3};"
        : "+f"(d[0]), "+f"(d[1]), "+f"(d[2]), "+f"(d[3])
        : "r"(__float_as_uint(a.x)), "r"(__float_as_uint(a.y)),
          "r"(__float_as_uint(a.z)), "r"(__float_as_uint(a.w)),
          "r"(__float_as_uint(b.x)), "r"(__float_as_uint(b.y)));
}
__device__ __forceinline__ uint32_t smem_u32(const void* p) {
    uint32_t a;
    asm("{ .reg .u64 t; cvta.to.shared.u64 t, %1; cvt.u32.u64 %0, t; }"
        : "=r"(a) : "l"(p));
    return a;
}
__device__ __forceinline__ void cp16(uint32_t dst, const void* src) {
    asm volatile("cp.async.cg.shared.global [%0], [%1], 16;"
                 :: "r"(dst), "l"(src) : "memory");
}
#define CP_COMMIT() asm volatile("cp.async.commit_group;" ::: "memory")
#define CP_WAIT(n)  asm volatile("cp.async.wait_group %0;" :: "n"(n) : "memory")

__device__ __forceinline__ unsigned enc(float f) {
    unsigned u = __float_as_uint(f);
    return (u & 0x80000000u) ? ~u : (u | 0x80000000u);
}
__device__ __forceinline__ float dec(unsigned u) {
    return (u & 0x80000000u) ? __uint_as_float(u & 0x7FFFFFFFu)
                             : __uint_as_float(~u);
}

// ---------------------------------------------------------------------------
__global__ __launch_bounds__(256) void prep_embed(const float* __restrict__ embed) {
    __shared__ float bmax[8];
    const int wid  = threadIdx.x >> 5;
    const int lane = threadIdx.x & 31;
    const int n = blockIdx.x * 8 + wid;

    const float* row = embed + (size_t)n * D_DIM;
    float s = 0.f;
    const float4* r4 = (const float4*)row;
    #pragma unroll
    for (int i = lane; i < 64; i += 32) {
        float4 v = r4[i];
        s += v.x * v.x + v.y * v.y + v.z * v.z + v.w * v.w;
    }
    #pragma unroll
    for (int o = 16; o; o >>= 1) s += __shfl_xor_sync(0xFFFFFFFFu, s, o);
    if (lane == 0) { g_esq[n] = s; bmax[wid] = s; }

    #pragma unroll
    for (int t = 0; t < 2; t++) {
        int p0 = lane * 8 + t * 4;
        float4 w;
        float* wp = (float*)&w;
        #pragma unroll
        for (int e = 0; e < 4; e++) {
            int p = p0 + e;
            int kc = p >> 5, r = p & 31;
            int j = r >> 3, kq = (r >> 1) & 3, h = r & 1;
            wp[e] = tf32_rn(__ldg(row + kc * 32 + j * 8 + kq + h * 4));
        }
        ((float4*)(g_bpk + (size_t)n * D_DIM))[p0 >> 2] = w;
    }

    __syncthreads();
    if (threadIdx.x == 0) {
        float m = bmax[0];
        #pragma unroll
        for (int i = 1; i < 8; i++) m = fmaxf(m, bmax[i]);
        atomicMax(&g_me2, __float_as_uint(m));
    }
}

__global__ __launch_bounds__(256) void prep_x(const float* __restrict__ x) {
    __shared__ float bmax[8];
    const int wid  = threadIdx.x >> 5;
    const int lane = threadIdx.x & 31;
    const int r = blockIdx.x * 8 + wid;

    const float4* r4 = (const float4*)(x + (size_t)r * D_DIM);
    float s = 0.f;
    #pragma unroll
    for (int i = lane; i < 64; i += 32) {
        float4 v = r4[i];
        s += v.x * v.x + v.y * v.y + v.z * v.z + v.w * v.w;
    }
    #pragma unroll
    for (int o = 16; o; o >>= 1) s += __shfl_xor_sync(0xFFFFFFFFu, s, o);
    if (lane == 0) { bmax[wid] = s; g_cnt[r] = 0; }

    __syncthreads();
    if (threadIdx.x == 0) {
        float m = bmax[0];
        #pragma unroll
        for (int i = 1; i < 8; i++) m = fmaxf(m, bmax[i]);
        atomicMax(&g_mx2, __float_as_uint(m));
    }
}

// ---------------------------------------------------------------------------
// Pass 1: 1xTF32 GEMM, 256 thr / 8 warps (2m x 4n), warp tile 32x64.
// 4-stage cp.async B pipeline; j-level register double-buffered fragments.
// ---------------------------------------------------------------------------
extern __shared__ float dsm[];

__device__ __forceinline__ void append_cand(int grow, int col) {
    int idx = atomicAdd(&g_cnt[grow], 1);
    if (idx < CAND_MAX) g_cand[grow * CAND_MAX + idx] = col;
}

__global__ __launch_bounds__(NTHREADS, 1) void vq1_kernel(
    const float* __restrict__ x)
{
    __shared__ unsigned red[TM];
    float* smA = dsm;
    const uint32_t smBase = smem_u32(dsm);

    const int tid  = threadIdx.x;
    const int lane = tid & 31;
    const int wid  = tid >> 5;
    const int wm   = wid & 1;          // m half  (32 rows)
    const int wn   = wid >> 1;         // n quarter (64 cols)
    const int mBase = blockIdx.x * TM;

    if (tid < TM) red[tid] = 0xFFFFFFFFu;

    const float th = 4.2e-3f * sqrtf(__uint_as_float(g_mx2) *
                                     __uint_as_float(g_me2)) + 0.02f;

    // prologue: issue B chunks 0..2 (all in n-tile 0)
    #pragma unroll
    for (int c0 = 0; c0 < 3; c0++) {
        uint32_t dstB = smBase + SM_A_FLOATS * 4 + (uint32_t)c0 * (BUF_FLOATS * 4);
        const float* src = g_bpk + c0 * KCH;
        #pragma unroll
        for (int i = 0; i < 8; i++) {
            int g = tid + i * NTHREADS, row = g >> 3, seg = g & 7;
            cp16(dstB + row * 160 + seg * 16, src + row * 256 + seg * 4);
        }
        CP_COMMIT();
    }

    // A: 64 rows x 256 k, tf32-rounded, mma-fragment-permuted
    #pragma unroll 4
    for (int s = 0; s < 16; s++) {
        int fidx = tid + s * NTHREADS;
        int row = fidx >> 6, q = fidx & 63;
        float4 v = ((const float4*)(x + (size_t)(mBase + row) * D_DIM))[q];
        int mt = row >> 4, ml = row & 15;
        float vv[4] = {v.x, v.y, v.z, v.w};
        #pragma unroll
        for (int e = 0; e < 4; e++) {
            int kk = q * 4 + e;
            int k8 = kk >> 3, c = kk & 7;
            int t    = ((ml & 7) << 2) | (c & 3);
            int slot = ((ml >> 3) & 1) | (((c >> 2) & 1) << 1);
            smA[(mt * 32 + k8) * 128 + t * 4 + slot] = tf32_rn(vv[e]);
        }
    }

    float acc[2][8][4];

    for (int c = 0; c < TOTCH; c++) {
        if (c + 2 < TOTCH)      CP_WAIT(2);
        else if (c + 1 < TOTCH) CP_WAIT(1);
        else                    CP_WAIT(0);
        __syncthreads();

        const int kc  = c & 7;
        const int ntB = (c >> 3) * TN;

        if (kc == 0) {
            #pragma unroll
            for (int i = 0; i < 2; i++)
                #pragma unroll
                for (int j = 0; j < 8; j++)
                    #pragma unroll
                    for (int e = 0; e < 4; e++) acc[i][j][e] = 0.f;
        }

        const float* bb = dsm + SM_A_FLOATS + (c % NBUF) * BUF_FLOATS;

        // ---- register double-buffered fragments over 4 k8 steps
        float4 afr[2][2];
        float2 bfr[2][8];
        {   // preload j = 0
            const int k8g = kc * 4;
            #pragma unroll
            for (int mt = 0; mt < 2; mt++)
                afr[0][mt] = *(const float4*)&smA[((wm * 2 + mt) * 32 + k8g) * 128
                                                  + lane * 4];
            #pragma unroll
            for (int ntl = 0; ntl < 8; ntl++)
                bfr[0][ntl] = *(const float2*)&bb[(wn * 64 + ntl * 8 + (lane >> 2)) * 40
                                                  + (lane & 3) * 2];
        }
        #pragma unroll
        for (int j = 0; j < 4; j++) {
            const int cur = j & 1, nx = cur ^ 1;
            if (j < 3) {
                const int k8g = kc * 4 + j + 1;
                #pragma unroll
                for (int mt = 0; mt < 2; mt++)
                    afr[nx][mt] = *(const float4*)&smA[((wm * 2 + mt) * 32 + k8g) * 128
                                                       + lane * 4];
                #pragma unroll
                for (int ntl = 0; ntl < 8; ntl++)
                    bfr[nx][ntl] = *(const float2*)&bb[(wn * 64 + ntl * 8 + (lane >> 2)) * 40
                                                       + ((j + 1) * 4 + (lane & 3)) * 2];
            }
            #pragma unroll
            for (int ntl = 0; ntl < 8; ntl++) {
                mma_f(acc[0][ntl], afr[cur][0], bfr[cur][ntl]);
                mma_f(acc[1][ntl], afr[cur][1], bfr[cur][ntl]);
            }
        }

        // refill freed buffer with chunk c+3
        if (c + 3 < TOTCH) {
            int nc = c + 3;
            uint32_t dstB = smBase + SM_A_FLOATS * 4
                          + (uint32_t)(nc % NBUF) * (BUF_FLOATS * 4);
            const float* src = g_bpk + (size_t)((nc >> 3) * TN) * 256
                             + (nc & 7) * KCH;
            #pragma unroll
            for (int i = 0; i < 8; i++) {
                int g = tid + i * NTHREADS, row = g >> 3, seg = g & 7;
                cp16(dstB + row * 160 + seg * 16, src + row * 256 + seg * 4);
            }
            CP_COMMIT();
        }

        if (kc == 7) {
            float rmin[4] = {3.4e38f, 3.4e38f, 3.4e38f, 3.4e38f};
            #pragma unroll
            for (int mt = 0; mt < 2; mt++)
                #pragma unroll
                for (int ntl = 0; ntl < 8; ntl++) {
                    int c0 = ntB + wn * 64 + ntl * 8 + 2 * (lane & 3);
                    float e0 = __ldg(&g_esq[c0]);
                    float e1 = __ldg(&g_esq[c0 + 1]);
                    float s0 = e0 - 2.0f * acc[mt][ntl][0];
                    float s1 = e1 - 2.0f * acc[mt][ntl][1];
                    float s2 = e0 - 2.0f * acc[mt][ntl][2];
                    float s3 = e1 - 2.0f * acc[mt][ntl][3];
                    rmin[mt*2]   = fminf(rmin[mt*2],   fminf(s0, s1));
                    rmin[mt*2+1] = fminf(rmin[mt*2+1], fminf(s2, s3));
                }
            #pragma unroll
            for (int q = 0; q < 4; q++) {
                int r = (wm * 2 + (q >> 1)) * 16 + (lane >> 2) + (q & 1) * 8;
                atomicMin(&red[r], enc(rmin[q]));
            }
            __syncthreads();
            #pragma unroll
            for (int mt = 0; mt < 2; mt++) {
                int r0 = (wm * 2 + mt) * 16 + (lane >> 2);
                float t0 = dec(red[r0]) + th;
                float t1 = dec(red[r0 + 8]) + th;
                #pragma unroll
                for (int ntl = 0; ntl < 8; ntl++) {
                    int c0 = ntB + wn * 64 + ntl * 8 + 2 * (lane & 3);
                    float e0 = __ldg(&g_esq[c0]);
                    float e1 = __ldg(&g_esq[c0 + 1]);
                    float s0 = e0 - 2.0f * acc[mt][ntl][0];
                    float s1 = e1 - 2.0f * acc[mt][ntl][1];
                    float s2 = e0 - 2.0f * acc[mt][ntl][2];
                    float s3 = e1 - 2.0f * acc[mt][ntl][3];
                    if (s0 <= t0) append_cand(mBase + r0, c0);
                    if (s1 <= t0) append_cand(mBase + r0, c0 + 1);
                    if (s2 <= t1) append_cand(mBase + r0 + 8, c0);
                    if (s3 <= t1) append_cand(mBase + r0 + 8, c0 + 1);
                }
            }
        }
    }
}

// ---------------------------------------------------------------------------
// Pass 2: fp32 rescore, warp per row, whole warp per candidate,
// next-candidate row prefetched into registers.
// ---------------------------------------------------------------------------
__global__ __launch_bounds__(256) void vq2_kernel(
    const float* __restrict__ x,
    const float* __restrict__ embed,
    float* __restrict__ out)
{
    const int wid  = threadIdx.x >> 5;
    const int lane = threadIdx.x & 31;
    const int R = blockIdx.x * 8 + wid;

    const float4* xr = (const float4*)(x + (size_t)R * D_DIM);
    float4 xa = xr[lane * 2], xb = xr[lane * 2 + 1];

    int cnt = g_cnt[R];
    float bd = 3.4e38f;
    int   bi = 0x7FFFFFFF;

    const bool uselist = (cnt <= CAND_MAX);
    const int  limit   = uselist ? cnt : N_TOT;
    const int* list    = g_cand + (size_t)R * CAND_MAX;

    int cd = uselist ? (limit > 0 ? list[0] : 0) : 0;
    const float4* er = (const float4*)(embed + (size_t)cd * D_DIM);
    float4 ea = er[lane * 2], eb = er[lane * 2 + 1];

    for (int ci = 0; ci < limit; ci++) {
        int curcd = cd;
        float4 ca = ea, cb = eb;
        if (ci + 1 < limit) {                 // prefetch next row
            cd = uselist ? list[ci + 1] : (ci + 1);
            er = (const float4*)(embed + (size_t)cd * D_DIM);
            ea = er[lane * 2]; eb = er[lane * 2 + 1];
        }
        float d0 = xa.x * ca.x + xa.y * ca.y + xa.z * ca.z + xa.w * ca.w;
        float d1 = xb.x * cb.x + xb.y * cb.y + xb.z * cb.z + xb.w * cb.w;
        float dot = d0 + d1;
        #pragma unroll
        for (int o = 16; o; o >>= 1)
            dot += __shfl_xor_sync(0xFFFFFFFFu, dot, o);
        float s = g_esq[curcd] - 2.0f * dot;
        if (s < bd || (s == bd && curcd < bi)) { bd = s; bi = curcd; }
    }

    if (lane == 0) out[(size_t)M_TOT * D_DIM + R] = (float)bi;

    const float4* src = (const float4*)(embed + (size_t)bi * D_DIM);
    float4* dst = (float4*)(out + (size_t)R * D_DIM);
    #pragma unroll
    for (int t = lane; t < 64; t += 32) dst[t] = src[t];
}

// ---------------------------------------------------------------------------
extern "C" void kernel_launch(void* const* d_in, const int* in_sizes, int n_in,
                              void* d_out, int out_size)
{
    const float* x     = (const float*)d_in[0];
    const float* embed = (const float*)d_in[1];
    float*       out   = (float*)d_out;

    prep_embed<<<N_TOT / 8, 256>>>(embed);
    prep_x<<<M_TOT / 8, 256>>>(x);

    cudaFuncSetAttribute(vq1_kernel,
                         cudaFuncAttributeMaxDynamicSharedMemorySize, SM_BYTES);
    vq1_kernel<<<M_TOT / TM, NTHREADS, SM_BYTES>>>(x);

    vq2_kernel<<<M_TOT / 8, 256>>>(x, embed, out);
}

// round 13
// speedup vs baseline: 1.1399x; 1.1399x over previous
#include <cuda_runtime.h>
#include <cuda_bf16.h>
#include <cstdint>
#include <math.h>

#define D_DIM    256
#define M_TOT    8192
#define N_TOT    8192
#define TM       64
#define TN       256
#define NTHREADS 256
#define TOTCH    ((N_TOT / TN) * 8)    // 256 chunks of 32 k
#define CAND_MAX 256
#define NBUF     4

#define SM_A_WORDS   8192              // bf16 A frags: 32 KB
#define BUF_WORDS    4096              // one B chunk: 16 KB
#define SM_BYTES     (4 * (SM_A_WORDS + NBUF * BUF_WORDS))   // 98304

__device__ uint32_t g_bpk[N_TOT * D_DIM / 2];   // bf16 B fragments
__device__ float    g_esq[N_TOT];
__device__ int      g_cand[M_TOT * CAND_MAX];
__device__ int      g_cnt[M_TOT];
__device__ unsigned g_mx2, g_me2;   // atomicMax-idempotent across graph replays

// ---------------------------------------------------------------------------
__device__ __forceinline__ uint32_t bf16x2(float lo, float hi) {
    uint32_t r;
    asm("cvt.rn.bf16x2.f32 %0, %1, %2;" : "=r"(r) : "f"(hi), "f"(lo));
    return r;
}
__device__ __forceinline__ void mma_bf16(float* d, uint4 a, uint2 b) {
    asm volatile(
        "mma.sync.aligned.m16n8k16.row.col.f32.bf16.bf16.f32 "
        "{%0,%1,%2,%3}, {%4,%5,%6,%7}, {%8,%9}, {%0,%1,%2,%3};"
        : "+f"(d[0]), "+f"(d[1]), "+f"(d[2]), "+f"(d[3])
        : "r"(a.x), "r"(a.y), "r"(a.z), "r"(a.w), "r"(b.x), "r"(b.y));
}
__device__ __forceinline__ uint32_t smem_u32(const void* p) {
    uint32_t a;
    asm("{ .reg .u64 t; cvta.to.shared.u64 t, %1; cvt.u32.u64 %0, t; }"
        : "=r"(a) : "l"(p));
    return a;
}
__device__ __forceinline__ void cp16(uint32_t dst, const void* src) {
    asm volatile("cp.async.cg.shared.global [%0], [%1], 16;"
                 :: "r"(dst), "l"(src) : "memory");
}
#define CP_COMMIT() asm volatile("cp.async.commit_group;" ::: "memory")
#define CP_WAIT(n)  asm volatile("cp.async.wait_group %0;" :: "n"(n) : "memory")

__device__ __forceinline__ unsigned enc(float f) {
    unsigned u = __float_as_uint(f);
    return (u & 0x80000000u) ? ~u : (u | 0x80000000u);
}
__device__ __forceinline__ float dec(unsigned u) {
    return (u & 0x80000000u) ? __uint_as_float(u & 0x7FFFFFFFu)
                             : __uint_as_float(~u);
}

// ---------------------------------------------------------------------------
// prep_embed: warp per code row -> esq, bf16 fragment-packed g_bpk, norm max
// g_bpk word index: chunk*4096 + k16*2048 + nloc*8 + tig*2 + w
//   w=0: {k=base+2tig, +1}, w=1: {k=base+2tig+8, +9}, base = kc*32 + k16*16
// ---------------------------------------------------------------------------
__global__ __launch_bounds__(256) void prep_embed(const float* __restrict__ embed) {
    __shared__ float bmax[8];
    const int wid  = threadIdx.x >> 5;
    const int lane = threadIdx.x & 31;
    const int n = blockIdx.x * 8 + wid;
    const int ntile = n >> 8, nloc = n & 255;

    const float* row = embed + (size_t)n * D_DIM;
    float s = 0.f;
    const float4* r4 = (const float4*)row;
    #pragma unroll
    for (int i = lane; i < 64; i += 32) {
        float4 v = r4[i];
        s += v.x * v.x + v.y * v.y + v.z * v.z + v.w * v.w;
    }
    #pragma unroll
    for (int o = 16; o; o >>= 1) s += __shfl_xor_sync(0xFFFFFFFFu, s, o);
    if (lane == 0) { g_esq[n] = s; bmax[wid] = s; }

    #pragma unroll
    for (int t = 0; t < 4; t++) {
        int widx = t * 32 + lane;          // 0..127
        int kc  = widx >> 4;
        int r   = widx & 15;
        int k16 = r >> 3;
        int r2  = r & 7;
        int tig = r2 >> 1;
        int w   = r2 & 1;
        int kb  = kc * 32 + k16 * 16 + tig * 2 + w * 8;
        uint32_t val = bf16x2(__ldg(row + kb), __ldg(row + kb + 1));
        g_bpk[(size_t)(ntile * 8 + kc) * 4096 + k16 * 2048 + nloc * 8 + tig * 2 + w] = val;
    }

    __syncthreads();
    if (threadIdx.x == 0) {
        float m = bmax[0];
        #pragma unroll
        for (int i = 1; i < 8; i++) m = fmaxf(m, bmax[i]);
        atomicMax(&g_me2, __float_as_uint(m));
    }
}

__global__ __launch_bounds__(256) void prep_x(const float* __restrict__ x) {
    __shared__ float bmax[8];
    const int wid  = threadIdx.x >> 5;
    const int lane = threadIdx.x & 31;
    const int r = blockIdx.x * 8 + wid;

    const float4* r4 = (const float4*)(x + (size_t)r * D_DIM);
    float s = 0.f;
    #pragma unroll
    for (int i = lane; i < 64; i += 32) {
        float4 v = r4[i];
        s += v.x * v.x + v.y * v.y + v.z * v.z + v.w * v.w;
    }
    #pragma unroll
    for (int o = 16; o; o >>= 1) s += __shfl_xor_sync(0xFFFFFFFFu, s, o);
    if (lane == 0) { bmax[wid] = s; g_cnt[r] = 0; }

    __syncthreads();
    if (threadIdx.x == 0) {
        float m = bmax[0];
        #pragma unroll
        for (int i = 1; i < 8; i++) m = fmaxf(m, bmax[i]);
        atomicMax(&g_mx2, __float_as_uint(m));
    }
}

// ---------------------------------------------------------------------------
// Pass 1: bf16 m16n8k16 screening GEMM, 256 thr / 8 warps (2m x 4n),
// warp tile 32x64. cp.async 4-buffer; per-chunk 2 k16 steps, reg-pipelined.
// ---------------------------------------------------------------------------
extern __shared__ uint32_t dsmw[];

__device__ __forceinline__ void append_cand(int grow, int col) {
    int idx = atomicAdd(&g_cnt[grow], 1);
    if (idx < CAND_MAX) g_cand[grow * CAND_MAX + idx] = col;
}

__global__ __launch_bounds__(NTHREADS, 1) void vq1_kernel(
    const float* __restrict__ x)
{
    __shared__ unsigned red[TM];
    uint32_t* smA = dsmw;
    const uint32_t smBase = smem_u32(dsmw);

    const int tid  = threadIdx.x;
    const int lane = tid & 31;
    const int wid  = tid >> 5;
    const int wm   = wid & 1;          // m half  (32 rows)
    const int wn   = wid >> 1;         // n quarter (64 cols)
    const int g    = lane >> 2;        // fragment groupID
    const int tig  = lane & 3;
    const int mBase = blockIdx.x * TM;

    if (tid < TM) red[tid] = 0xFFFFFFFFu;

    // bf16 screening bound: 2*E, E = 2*(2*2^-9 + 2^-16)*||x||*||e||
    const float th = 0.0316f * sqrtf(__uint_as_float(g_mx2) *
                                     __uint_as_float(g_me2)) + 0.25f;

    // prologue: issue B chunks 0..2 (16 KB each, contiguous in g_bpk)
    #pragma unroll
    for (int c0 = 0; c0 < 3; c0++) {
        uint32_t dstB = smBase + SM_A_WORDS * 4 + (uint32_t)c0 * (BUF_WORDS * 4);
        const char* src = (const char*)g_bpk + (size_t)c0 * 16384;
        #pragma unroll
        for (int i = 0; i < 4; i++)
            cp16(dstB + i * 4096 + tid * 16, src + i * 4096 + tid * 16);
        CP_COMMIT();
    }

    // A: 64 rows x 256 k -> bf16 fragment-packed (16B per lane per [mt][k16])
    #pragma unroll 4
    for (int s = 0; s < 16; s++) {
        int fidx = s * NTHREADS + tid;
        int row = fidx >> 6, q = fidx & 63;
        float4 v = ((const float4*)(x + (size_t)(mBase + row) * D_DIM))[q];
        int mt = row >> 4, ml = row & 15;
        int gr = ml & 7, half = ml >> 3;
        int k0 = q * 4;
        int k16 = k0 >> 4, kl = k0 & 15;
        int hi8 = kl >> 3, tg0 = (kl & 7) >> 1;
        int reg = hi8 * 2 + half;
        int idx0 = ((mt * 16 + k16) * 32 + gr * 4 + tg0) * 4 + reg;
        smA[idx0]     = bf16x2(v.x, v.y);
        smA[idx0 + 4] = bf16x2(v.z, v.w);
    }

    float acc[2][8][4];

    for (int c = 0; c < TOTCH; c++) {
        if (c + 2 < TOTCH)      CP_WAIT(2);
        else if (c + 1 < TOTCH) CP_WAIT(1);
        else                    CP_WAIT(0);
        __syncthreads();

        const int kc  = c & 7;
        const int ntB = (c >> 3) * TN;

        if (kc == 0) {
            #pragma unroll
            for (int i = 0; i < 2; i++)
                #pragma unroll
                for (int j = 0; j < 8; j++)
                    #pragma unroll
                    for (int e = 0; e < 4; e++) acc[i][j][e] = 0.f;
        }

        const uint32_t* bb = dsmw + SM_A_WORDS + (c % NBUF) * BUF_WORDS;
        const uint4* smA4 = (const uint4*)smA;

        // 2 k16 steps, register double-buffered fragments
        uint4 afr[2][2];
        uint2 bfr[2][8];
        #pragma unroll
        for (int mt = 0; mt < 2; mt++)
            afr[0][mt] = smA4[((wm * 2 + mt) * 16 + kc * 2) * 32 + lane];
        #pragma unroll
        for (int ntl = 0; ntl < 8; ntl++)
            bfr[0][ntl] = *(const uint2*)&bb[(wn * 64 + ntl * 8 + g) * 8 + tig * 2];

        #pragma unroll
        for (int j = 0; j < 2; j++) {
            if (j == 0) {
                #pragma unroll
                for (int mt = 0; mt < 2; mt++)
                    afr[1][mt] = smA4[((wm * 2 + mt) * 16 + kc * 2 + 1) * 32 + lane];
                #pragma unroll
                for (int ntl = 0; ntl < 8; ntl++)
                    bfr[1][ntl] = *(const uint2*)&bb[2048 +
                        (wn * 64 + ntl * 8 + g) * 8 + tig * 2];
            }
            #pragma unroll
            for (int ntl = 0; ntl < 8; ntl++) {
                mma_bf16(acc[0][ntl], afr[j][0], bfr[j][ntl]);
                mma_bf16(acc[1][ntl], afr[j][1], bfr[j][ntl]);
            }
        }

        // refill freed buffer with chunk c+3
        if (c + 3 < TOTCH) {
            int nc = c + 3;
            uint32_t dstB = smBase + SM_A_WORDS * 4
                          + (uint32_t)(nc % NBUF) * (BUF_WORDS * 4);
            const char* src = (const char*)g_bpk + (size_t)nc * 16384;
            #pragma unroll
            for (int i = 0; i < 4; i++)
                cp16(dstB + i * 4096 + tid * 16, src + i * 4096 + tid * 16);
            CP_COMMIT();
        }

        if (kc == 7) {
            float rmin[4] = {3.4e38f, 3.4e38f, 3.4e38f, 3.4e38f};
            #pragma unroll
            for (int mt = 0; mt < 2; mt++)
                #pragma unroll
                for (int ntl = 0; ntl < 8; ntl++) {
                    int c0 = ntB + wn * 64 + ntl * 8 + 2 * tig;
                    float e0 = __ldg(&g_esq[c0]);
                    float e1 = __ldg(&g_esq[c0 + 1]);
                    float s0 = e0 - 2.0f * acc[mt][ntl][0];
                    float s1 = e1 - 2.0f * acc[mt][ntl][1];
                    float s2 = e0 - 2.0f * acc[mt][ntl][2];
                    float s3 = e1 - 2.0f * acc[mt][ntl][3];
                    rmin[mt*2]   = fminf(rmin[mt*2],   fminf(s0, s1));
                    rmin[mt*2+1] = fminf(rmin[mt*2+1], fminf(s2, s3));
                }
            #pragma unroll
            for (int q = 0; q < 4; q++) {
                int r = (wm * 2 + (q >> 1)) * 16 + g + (q & 1) * 8;
                atomicMin(&red[r], enc(rmin[q]));
            }
            __syncthreads();
            #pragma unroll
            for (int mt = 0; mt < 2; mt++) {
                int r0 = (wm * 2 + mt) * 16 + g;
                float t0 = dec(red[r0]) + th;
                float t1 = dec(red[r0 + 8]) + th;
                #pragma unroll
                for (int ntl = 0; ntl < 8; ntl++) {
                    int c0 = ntB + wn * 64 + ntl * 8 + 2 * tig;
                    float e0 = __ldg(&g_esq[c0]);
                    float e1 = __ldg(&g_esq[c0 + 1]);
                    float s0 = e0 - 2.0f * acc[mt][ntl][0];
                    float s1 = e1 - 2.0f * acc[mt][ntl][1];
                    float s2 = e0 - 2.0f * acc[mt][ntl][2];
                    float s3 = e1 - 2.0f * acc[mt][ntl][3];
                    if (s0 <= t0) append_cand(mBase + r0, c0);
                    if (s1 <= t0) append_cand(mBase + r0, c0 + 1);
                    if (s2 <= t1) append_cand(mBase + r0 + 8, c0);
                    if (s3 <= t1) append_cand(mBase + r0 + 8, c0 + 1);
                }
            }
        }
    }
}

// ---------------------------------------------------------------------------
// Pass 2: fp32 rescore, warp per row, whole warp per candidate,
// next-candidate row prefetched into registers.
// ---------------------------------------------------------------------------
__global__ __launch_bounds__(256) void vq2_kernel(
    const float* __restrict__ x,
    const float* __restrict__ embed,
    float* __restrict__ out)
{
    const int wid  = threadIdx.x >> 5;
    const int lane = threadIdx.x & 31;
    const int R = blockIdx.x * 8 + wid;

    const float4* xr = (const float4*)(x + (size_t)R * D_DIM);
    float4 xa = xr[lane * 2], xb = xr[lane * 2 + 1];

    int cnt = g_cnt[R];
    float bd = 3.4e38f;
    int   bi = 0x7FFFFFFF;

    const bool uselist = (cnt <= CAND_MAX);
    const int  limit   = uselist ? cnt : N_TOT;
    const int* list    = g_cand + (size_t)R * CAND_MAX;

    int cd = uselist ? (limit > 0 ? list[0] : 0) : 0;
    const float4* er = (const float4*)(embed + (size_t)cd * D_DIM);
    float4 ea = er[lane * 2], eb = er[lane * 2 + 1];

    for (int ci = 0; ci < limit; ci++) {
        int curcd = cd;
        float4 ca = ea, cb = eb;
        if (ci + 1 < limit) {                 // prefetch next row
            cd = uselist ? list[ci + 1] : (ci + 1);
            er = (const float4*)(embed + (size_t)cd * D_DIM);
            ea = er[lane * 2]; eb = er[lane * 2 + 1];
        }
        float d0 = xa.x * ca.x + xa.y * ca.y + xa.z * ca.z + xa.w * ca.w;
        float d1 = xb.x * cb.x + xb.y * cb.y + xb.z * cb.z + xb.w * cb.w;
        float dot = d0 + d1;
        #pragma unroll
        for (int o = 16; o; o >>= 1)
            dot += __shfl_xor_sync(0xFFFFFFFFu, dot, o);
        float s = g_esq[curcd] - 2.0f * dot;
        if (s < bd || (s == bd && curcd < bi)) { bd = s; bi = curcd; }
    }

    if (lane == 0) out[(size_t)M_TOT * D_DIM + R] = (float)bi;

    const float4* src = (const float4*)(embed + (size_t)bi * D_DIM);
    float4* dst = (float4*)(out + (size_t)R * D_DIM);
    #pragma unroll
    for (int t = lane; t < 64; t += 32) dst[t] = src[t];
}

// ---------------------------------------------------------------------------
extern "C" void kernel_launch(void* const* d_in, const int* in_sizes, int n_in,
                              void* d_out, int out_size)
{
    const float* x     = (const float*)d_in[0];
    const float* embed = (const float*)d_in[1];
    float*       out   = (float*)d_out;

    prep_embed<<<N_TOT / 8, 256>>>(embed);
    prep_x<<<M_TOT / 8, 256>>>(x);

    cudaFuncSetAttribute(vq1_kernel,
                         cudaFuncAttributeMaxDynamicSharedMemorySize, SM_BYTES);
    vq1_kernel<<<M_TOT / TM, NTHREADS, SM_BYTES>>>(x);

    vq2_kernel<<<M_TOT / 8, 256>>>(x, embed, out);
}